// round 5
// baseline (speedup 1.0000x reference)
#include <cuda_runtime.h>
#include <math.h>

#define S3 262144        // 64^3
#define NMODE 6912       // 4 corners * 1728

// ---------------- scratch ----------------
__device__ float  g_v[64*S3];
__device__ float  g_s[64*S3];
__device__ float2 g_B[64*64*288];
__device__ float2 g_X[64*NMODE];   // corner-major: c*NMODE + corner*1728 + cmode
__device__ float2 g_Y[64*NMODE];
__device__ float  g_h1[1024];
__device__ float  g_film[384];
__device__ double g_gn[16];
__device__ float  g_gnf[16];
__device__ __align__(16) float2 tw_fWt[64*12];   // [w][kw]  fwd W twiddle, transposed
__device__ __align__(16) float2 tw_iW[12*64];    // [kw][w]  inv W twiddle * alpha/64^3
__device__ __align__(16) float2 tw_fDHt[64*24];  // [x][j]   fwd D/H twiddle, transposed
__device__ __align__(16) float2 tw_iDH[24*64];   // [j][x]   inv D/H twiddle

__device__ __forceinline__ float gelu_f(float x){
    return 0.5f*x*(1.0f + erff(x*0.7071067811865476f));
}

#define CMAC(acc, a, t) { acc.x += a.x*t.x - a.y*t.y; acc.y += a.x*t.y + a.y*t.x; }

// ---------------- tables ----------------
__global__ void init_tables_k(){
    int t = blockIdx.x*blockDim.x + threadIdx.x;
    const double w0 = 6.283185307179586476925286766559/64.0;
    if(t < 768){
        int kw = t>>6, w = t&63;
        double s,c; sincos(w0*(double)(kw*w), &s, &c);
        tw_fWt[w*12+kw] = make_float2((float)c, (float)(-s));
        double al = (kw==0 ? 1.0 : 2.0) / 262144.0;
        tw_iW[kw*64+w] = make_float2((float)(al*c), (float)(al*s));
    }
    if(t < 1536){
        int j = t>>6, x = t&63;
        int bin = (j<12) ? j : (j+40);
        double s,c; sincos(w0*(double)(bin*x), &s, &c);
        tw_fDHt[x*24+j] = make_float2((float)c, (float)(-s));
        tw_iDH[j*64+x]  = make_float2((float)c, (float)( s));
    }
    if(t < 16) g_gn[t] = 0.0;
}

// ---------------- FiLM ----------------
__global__ void film1_k(const float* __restrict__ latent, const float* __restrict__ w,
                        const float* __restrict__ b){
    int wid  = (blockIdx.x*blockDim.x + threadIdx.x) >> 5;
    int lane = threadIdx.x & 31;
    if(wid >= 1024) return;
    const float* wr = w + wid*512;
    float acc = 0.f;
    for(int k=lane;k<512;k+=32) acc += latent[k]*wr[k];
    #pragma unroll
    for(int o=16;o;o>>=1) acc += __shfl_xor_sync(0xffffffffu, acc, o);
    if(lane==0) g_h1[wid] = gelu_f(acc + b[wid]);
}
__global__ void film2_k(const float* __restrict__ w, const float* __restrict__ b){
    int wid  = (blockIdx.x*blockDim.x + threadIdx.x) >> 5;
    int lane = threadIdx.x & 31;
    if(wid >= 384) return;
    const float* wr = w + wid*1024;
    float acc = 0.f;
    for(int k=lane;k<1024;k+=32) acc += g_h1[k]*wr[k];
    #pragma unroll
    for(int o=16;o;o>>=1) acc += __shfl_xor_sync(0xffffffffu, acc, o);
    if(lane==0) g_film[wid] = acc + b[wid];
}

// ---------------- lift + conv(layer0), register-tiled, transposed weights ----------------
__global__ void __launch_bounds__(256) lift_conv_k(const float* __restrict__ x,
        const float* __restrict__ lw, const float* __restrict__ lb,
        const float* __restrict__ cw, const float* __restrict__ cb){
    int s0 = blockIdx.x*128;
    __shared__ float vsh[64][128];
    __shared__ float wshT[64][68];
    int s = threadIdx.x & 127, chalf = threadIdx.x >> 7;
    float x0 = __ldg(&x[s0+s]),        x1 = __ldg(&x[S3+s0+s]);
    float x2 = __ldg(&x[2*S3+s0+s]),   x3 = __ldg(&x[3*S3+s0+s]);
    for(int i=threadIdx.x;i<4096;i+=256) wshT[i&63][i>>6] = cw[i];
    #pragma unroll
    for(int i=0;i<32;i++){
        int cc = i*2 + chalf;
        float v = __ldg(&lb[cc]) + __ldg(&lw[cc*4+0])*x0 + __ldg(&lw[cc*4+1])*x1
                                 + __ldg(&lw[cc*4+2])*x2 + __ldg(&lw[cc*4+3])*x3;
        vsh[cc][s] = v;
        g_v[(size_t)cc*S3 + s0 + s] = v;
    }
    __syncthreads();
    int o0 = (threadIdx.x>>5)*8, si = (threadIdx.x&31)*4;
    float acc[8][4];
    #pragma unroll
    for(int a=0;a<8;a++){ acc[a][0]=0.f;acc[a][1]=0.f;acc[a][2]=0.f;acc[a][3]=0.f; }
    for(int k=0;k<64;k++){
        float4 v4 = *(const float4*)&vsh[k][si];
        float4 wa = *(const float4*)&wshT[k][o0];
        float4 wb = *(const float4*)&wshT[k][o0+4];
        acc[0][0]+=wa.x*v4.x; acc[0][1]+=wa.x*v4.y; acc[0][2]+=wa.x*v4.z; acc[0][3]+=wa.x*v4.w;
        acc[1][0]+=wa.y*v4.x; acc[1][1]+=wa.y*v4.y; acc[1][2]+=wa.y*v4.z; acc[1][3]+=wa.y*v4.w;
        acc[2][0]+=wa.z*v4.x; acc[2][1]+=wa.z*v4.y; acc[2][2]+=wa.z*v4.z; acc[2][3]+=wa.z*v4.w;
        acc[3][0]+=wa.w*v4.x; acc[3][1]+=wa.w*v4.y; acc[3][2]+=wa.w*v4.z; acc[3][3]+=wa.w*v4.w;
        acc[4][0]+=wb.x*v4.x; acc[4][1]+=wb.x*v4.y; acc[4][2]+=wb.x*v4.z; acc[4][3]+=wb.x*v4.w;
        acc[5][0]+=wb.y*v4.x; acc[5][1]+=wb.y*v4.y; acc[5][2]+=wb.y*v4.z; acc[5][3]+=wb.y*v4.w;
        acc[6][0]+=wb.z*v4.x; acc[6][1]+=wb.z*v4.y; acc[6][2]+=wb.z*v4.z; acc[6][3]+=wb.z*v4.w;
        acc[7][0]+=wb.w*v4.x; acc[7][1]+=wb.w*v4.y; acc[7][2]+=wb.w*v4.z; acc[7][3]+=wb.w*v4.w;
    }
    #pragma unroll
    for(int oi=0;oi<8;oi++){
        float bb = __ldg(&cb[o0+oi]);
        *(float4*)&g_s[(size_t)(o0+oi)*S3 + s0 + si] =
            make_float4(acc[oi][0]+bb, acc[oi][1]+bb, acc[oi][2]+bb, acc[oi][3]+bb);
    }
}

// ---------------- fused forward DFT: W then H (twiddles via __ldg/L1) ----------------
__global__ void __launch_bounds__(128) fwdWH_k(){
    int d = blockIdx.x, c = blockIdx.y;
    __shared__ float vsh[64][65];
    __shared__ float2 Ash[12][64];
    const float4* src = (const float4*)(g_v + (size_t)(c*64+d)*4096);
    for(int i=threadIdx.x;i<1024;i+=128){
        float4 v4 = src[i];
        int h = i>>4, w4 = (i&15)*4;
        vsh[h][w4]=v4.x; vsh[h][w4+1]=v4.y; vsh[h][w4+2]=v4.z; vsh[h][w4+3]=v4.w;
    }
    __syncthreads();
    {
        int h = threadIdx.x & 63, kw0 = (threadIdx.x>>6)*6;
        float2 a0={0,0},a1={0,0},a2={0,0},a3={0,0},a4={0,0},a5={0,0};
        for(int w=0;w<64;w++){
            float v = vsh[h][w];
            const float4* tp = (const float4*)(tw_fWt + w*12 + kw0);
            float4 t0 = __ldg(tp), t1 = __ldg(tp+1), t2 = __ldg(tp+2);
            a0.x += v*t0.x; a0.y += v*t0.y; a1.x += v*t0.z; a1.y += v*t0.w;
            a2.x += v*t1.x; a2.y += v*t1.y; a3.x += v*t1.z; a3.y += v*t1.w;
            a4.x += v*t2.x; a4.y += v*t2.y; a5.x += v*t2.z; a5.y += v*t2.w;
        }
        Ash[kw0+0][h]=a0; Ash[kw0+1][h]=a1; Ash[kw0+2][h]=a2;
        Ash[kw0+3][h]=a3; Ash[kw0+4][h]=a4; Ash[kw0+5][h]=a5;
    }
    __syncthreads();
    if(threadIdx.x < 96){
        int kw = threadIdx.x % 12, jh0 = (threadIdx.x/12)*3;
        float2 b0={0,0},b1={0,0},b2={0,0};
        for(int h=0;h<64;h++){
            float2 a = Ash[kw][h];
            float2 t0 = __ldg(&tw_fDHt[h*24+jh0]);
            float2 t1 = __ldg(&tw_fDHt[h*24+jh0+1]);
            float2 t2 = __ldg(&tw_fDHt[h*24+jh0+2]);
            CMAC(b0,a,t0); CMAC(b1,a,t1); CMAC(b2,a,t2);
        }
        float2* dst = g_B + (size_t)(c*64+d)*288;
        dst[jh0*12+kw]=b0; dst[(jh0+1)*12+kw]=b1; dst[(jh0+2)*12+kw]=b2;
    }
}

// ---------------- forward DFT over D (stores corner-major) ----------------
__global__ void __launch_bounds__(128) fwdD_k(){
    int jh = blockIdx.x, c = blockIdx.y;
    __shared__ float2 Bsh[64][12];
    for(int i=threadIdx.x;i<768;i+=128){
        int d = i/12, kw = i - d*12;
        Bsh[d][kw] = g_B[(size_t)(c*64+d)*288 + jh*12 + kw];
    }
    __syncthreads();
    if(threadIdx.x < 96){
        int kw = threadIdx.x % 12, jd0 = (threadIdx.x/12)*3;
        float2 b0={0,0},b1={0,0},b2={0,0};
        for(int d=0;d<64;d++){
            float2 a = Bsh[d][kw];
            float2 t0 = __ldg(&tw_fDHt[d*24+jd0]);
            float2 t1 = __ldg(&tw_fDHt[d*24+jd0+1]);
            float2 t2 = __ldg(&tw_fDHt[d*24+jd0+2]);
            CMAC(b0,a,t0); CMAC(b1,a,t1); CMAC(b2,a,t2);
        }
        int jhm = jh % 12, cbase = (jh>=12) ? 2 : 0;
        #pragma unroll
        for(int r=0;r<3;r++){
            int jd = jd0 + r;
            int corner = cbase + (jd>=12 ? 1 : 0);
            int cmode = ((jd%12)*12 + jhm)*12 + kw;
            float2 b = (r==0)?b0:(r==1)?b1:b2;
            g_X[(size_t)c*NMODE + corner*1728 + cmode] = b;
        }
    }
}

// ---------------- per-mode channel mix: float4 streaming ----------------
__global__ void __launch_bounds__(256) mix_k(const float* __restrict__ w1, const float* __restrict__ w2,
                                             const float* __restrict__ w3, const float* __restrict__ w4){
    int corner = blockIdx.x / 27;
    int c0 = (blockIdx.x - corner*27) * 64;
    const float* wbase = (corner==0)?w1:(corner==1)?w2:(corner==2)?w3:w4;
    __shared__ float2 xs[64][64];
    int tx = threadIdx.x & 31, ty = threadIdx.x >> 5;
    for(int i=ty; i<64; i+=8)
        ((float4*)xs[i])[tx] = *(const float4*)(&g_X[(size_t)i*NMODE + corner*1728 + c0 + tx*2]);
    __syncthreads();
    int o = blockIdx.y*8 + ty;
    const float* Wp = wbase + ((size_t)o*1728 + c0 + tx*2)*2;
    float re0=0.f,im0=0.f,re1=0.f,im1=0.f;
    #pragma unroll 8
    for(int i=0;i<64;i++){
        float4 wv = *(const float4*)(Wp + (size_t)i*221184);
        float4 xx = ((const float4*)xs[i])[tx];
        re0 += xx.x*wv.x - xx.y*wv.y; im0 += xx.x*wv.y + xx.y*wv.x;
        re1 += xx.z*wv.z - xx.w*wv.w; im1 += xx.z*wv.w + xx.w*wv.z;
    }
    *(float4*)(&g_Y[(size_t)o*NMODE + corner*1728 + c0 + tx*2]) = make_float4(re0,im0,re1,im1);
}

// ---------------- inverse DFT over D (reads corner-major) ----------------
__global__ void __launch_bounds__(128) invD_k(){
    int jh = blockIdx.x, c = blockIdx.y;
    __shared__ __align__(16) float2 Ysh[24][12];
    int jhm = jh % 12, cbase = (jh>=12) ? 2 : 0;
    for(int i=threadIdx.x;i<288;i+=128){
        int jd = i/12, kw = i - jd*12;
        int corner = cbase + (jd>=12 ? 1 : 0);
        int cmode = ((jd%12)*12 + jhm)*12 + kw;
        Ysh[jd][kw] = g_Y[(size_t)c*NMODE + corner*1728 + cmode];
    }
    __syncthreads();
    int d = threadIdx.x & 63, kw0 = (threadIdx.x>>6)*6;
    float2 a0={0,0},a1={0,0},a2={0,0},a3={0,0},a4={0,0},a5={0,0};
    for(int jd=0;jd<24;jd++){
        float2 t = __ldg(&tw_iDH[jd*64+d]);
        const float4* yp = (const float4*)(&Ysh[jd][kw0]);
        float4 y0 = yp[0], y1 = yp[1], y2 = yp[2];
        float2 v;
        v = make_float2(y0.x,y0.y); CMAC(a0,v,t);
        v = make_float2(y0.z,y0.w); CMAC(a1,v,t);
        v = make_float2(y1.x,y1.y); CMAC(a2,v,t);
        v = make_float2(y1.z,y1.w); CMAC(a3,v,t);
        v = make_float2(y2.x,y2.y); CMAC(a4,v,t);
        v = make_float2(y2.z,y2.w); CMAC(a5,v,t);
    }
    float2* dst = g_B + (size_t)(c*64+d)*288 + jh*12 + kw0;
    dst[0]=a0; dst[1]=a1; dst[2]=a2; dst[3]=a3; dst[4]=a4; dst[5]=a5;
}

// ---------------- fused inverse H + W + residual add + GN stats ----------------
__global__ void __launch_bounds__(128) invHW_gn_k(){
    int d = blockIdx.x, c = blockIdx.y;
    __shared__ __align__(16) float2 Bsh[288];
    __shared__ float2 Ash[12][64];
    __shared__ float redS[4], redQ[4];
    const float2* src = g_B + (size_t)(c*64+d)*288;
    for(int i=threadIdx.x;i<288;i+=128)  Bsh[i] = src[i];
    __syncthreads();
    {
        int h = threadIdx.x & 63, kw0 = (threadIdx.x>>6)*6;
        float2 a0={0,0},a1={0,0},a2={0,0},a3={0,0},a4={0,0},a5={0,0};
        for(int jh=0;jh<24;jh++){
            float2 t = __ldg(&tw_iDH[jh*64+h]);
            const float4* bp = (const float4*)(&Bsh[jh*12+kw0]);
            float4 b0 = bp[0], b1 = bp[1], b2 = bp[2];
            float2 v;
            v = make_float2(b0.x,b0.y); CMAC(a0,v,t);
            v = make_float2(b0.z,b0.w); CMAC(a1,v,t);
            v = make_float2(b1.x,b1.y); CMAC(a2,v,t);
            v = make_float2(b1.z,b1.w); CMAC(a3,v,t);
            v = make_float2(b2.x,b2.y); CMAC(a4,v,t);
            v = make_float2(b2.z,b2.w); CMAC(a5,v,t);
        }
        Ash[kw0+0][h]=a0; Ash[kw0+1][h]=a1; Ash[kw0+2][h]=a2;
        Ash[kw0+3][h]=a3; Ash[kw0+4][h]=a4; Ash[kw0+5][h]=a5;
    }
    __syncthreads();
    int wp = threadIdx.x & 31, hg = threadIdx.x >> 5;
    float2 tA[12], tB[12];
    #pragma unroll
    for(int kw=0;kw<12;kw++){ tA[kw]=__ldg(&tw_iW[kw*64+wp*2]); tB[kw]=__ldg(&tw_iW[kw*64+wp*2+1]); }
    float ssum=0.f, sq=0.f;
    float2* srow = (float2*)(g_s + (size_t)c*S3 + d*4096);
    for(int h=hg*16; h<hg*16+16; h++){
        float r0=0.f, r1=0.f;
        #pragma unroll
        for(int kw=0;kw<12;kw++){
            float2 a = Ash[kw][h];
            r0 += a.x*tA[kw].x - a.y*tA[kw].y;
            r1 += a.x*tB[kw].x - a.y*tB[kw].y;
        }
        float2 sv = srow[h*32+wp];
        sv.x += r0; sv.y += r1;
        srow[h*32+wp] = sv;
        ssum += sv.x + sv.y; sq += sv.x*sv.x + sv.y*sv.y;
    }
    #pragma unroll
    for(int o=16;o;o>>=1){ ssum += __shfl_xor_sync(0xffffffffu,ssum,o);
                           sq   += __shfl_xor_sync(0xffffffffu,sq,o); }
    if(wp==0){ redS[hg]=ssum; redQ[hg]=sq; }
    __syncthreads();
    if(threadIdx.x==0){
        float S = redS[0]+redS[1]+redS[2]+redS[3];
        float Q = redQ[0]+redQ[1]+redQ[2]+redQ[3];
        int g = c>>3;
        atomicAdd(&g_gn[g*2],   (double)S);
        atomicAdd(&g_gn[g*2+1], (double)Q);
    }
}

__global__ void gn_final_k(){
    int g = threadIdx.x;
    float mu_f=0.f, rs_f=0.f;
    if(g<8){
        double n = 8.0*(double)S3;
        double mu = g_gn[g*2]/n;
        double var = g_gn[g*2+1]/n - mu*mu;
        mu_f = (float)mu; rs_f = (float)(1.0/sqrt(var + 1e-5));
    }
    __syncthreads();
    if(g<8){ g_gnf[g*2]=mu_f; g_gnf[g*2+1]=rs_f; }
    if(g<16) g_gn[g]=0.0;
}

// ---------------- GN-apply + GELU + FiLM + conv(next layer) ----------------
__global__ void __launch_bounds__(256) gn_apply_conv_k(const float* __restrict__ gg, const float* __restrict__ gb,
        int l, const float* __restrict__ cw, const float* __restrict__ cb){
    int s0 = blockIdx.x*128;
    __shared__ float vsh[64][128];
    __shared__ float wshT[64][68];
    int s = threadIdx.x & 127, chalf = threadIdx.x >> 7;
    for(int i=threadIdx.x;i<4096;i+=256) wshT[i&63][i>>6] = cw[i];
    #pragma unroll
    for(int i=0;i<32;i++){
        int cc = i*2 + chalf;
        int g = cc>>3;
        float xv = (g_s[(size_t)cc*S3+s0+s]-g_gnf[g*2])*g_gnf[g*2+1]*__ldg(&gg[cc]) + __ldg(&gb[cc]);
        float y = gelu_f(xv);
        float v = y*(1.f+g_film[(l*64+cc)*2]) + g_film[(l*64+cc)*2+1];
        vsh[cc][s] = v;
        g_v[(size_t)cc*S3+s0+s] = v;
    }
    __syncthreads();
    int o0 = (threadIdx.x>>5)*8, si = (threadIdx.x&31)*4;
    float acc[8][4];
    #pragma unroll
    for(int a=0;a<8;a++){ acc[a][0]=0.f;acc[a][1]=0.f;acc[a][2]=0.f;acc[a][3]=0.f; }
    for(int k=0;k<64;k++){
        float4 v4 = *(const float4*)&vsh[k][si];
        float4 wa = *(const float4*)&wshT[k][o0];
        float4 wb = *(const float4*)&wshT[k][o0+4];
        acc[0][0]+=wa.x*v4.x; acc[0][1]+=wa.x*v4.y; acc[0][2]+=wa.x*v4.z; acc[0][3]+=wa.x*v4.w;
        acc[1][0]+=wa.y*v4.x; acc[1][1]+=wa.y*v4.y; acc[1][2]+=wa.y*v4.z; acc[1][3]+=wa.y*v4.w;
        acc[2][0]+=wa.z*v4.x; acc[2][1]+=wa.z*v4.y; acc[2][2]+=wa.z*v4.z; acc[2][3]+=wa.z*v4.w;
        acc[3][0]+=wa.w*v4.x; acc[3][1]+=wa.w*v4.y; acc[3][2]+=wa.w*v4.z; acc[3][3]+=wa.w*v4.w;
        acc[4][0]+=wb.x*v4.x; acc[4][1]+=wb.x*v4.y; acc[4][2]+=wb.x*v4.z; acc[4][3]+=wb.x*v4.w;
        acc[5][0]+=wb.y*v4.x; acc[5][1]+=wb.y*v4.y; acc[5][2]+=wb.y*v4.z; acc[5][3]+=wb.y*v4.w;
        acc[6][0]+=wb.z*v4.x; acc[6][1]+=wb.z*v4.y; acc[6][2]+=wb.z*v4.z; acc[6][3]+=wb.z*v4.w;
        acc[7][0]+=wb.w*v4.x; acc[7][1]+=wb.w*v4.y; acc[7][2]+=wb.w*v4.z; acc[7][3]+=wb.w*v4.w;
    }
    #pragma unroll
    for(int oi=0;oi<8;oi++){
        float bb = __ldg(&cb[o0+oi]);
        *(float4*)&g_s[(size_t)(o0+oi)*S3 + s0 + si] =
            make_float4(acc[oi][0]+bb, acc[oi][1]+bb, acc[oi][2]+bb, acc[oi][3]+bb);
    }
}

// ---------------- last layer: GN-apply + FiLM + p1 + GELU + p2 ----------------
__global__ void __launch_bounds__(256) gn_apply_head_k(const float* __restrict__ gg, const float* __restrict__ gb,
        int l, const float* __restrict__ w1, const float* __restrict__ b1,
        const float* __restrict__ w2, const float* __restrict__ b2, float* __restrict__ out){
    int s0 = blockIdx.x*64;
    __shared__ float vsh[64][64];
    __shared__ float wshT[64][68];
    __shared__ float w2s[3][128];
    __shared__ float red[16][3][64];
    int s = threadIdx.x & 63, cq = threadIdx.x >> 6;
    for(int i=threadIdx.x;i<384;i+=256){ int j=i>>7, o=i&127; w2s[j][o]=w2[j*128+o]; }
    #pragma unroll
    for(int i=0;i<16;i++){
        int cc = i*4 + cq;
        int g = cc>>3;
        float xv = (g_s[(size_t)cc*S3+s0+s]-g_gnf[g*2])*g_gnf[g*2+1]*__ldg(&gg[cc]) + __ldg(&gb[cc]);
        float y = gelu_f(xv);
        vsh[cc][s] = y*(1.f+g_film[(l*64+cc)*2]) + g_film[(l*64+cc)*2+1];
    }
    int og = threadIdx.x >> 4, sg = threadIdx.x & 15;
    int o0 = og*4, si = sg*4;
    float p[3][4];
    #pragma unroll
    for(int j=0;j<3;j++){ p[j][0]=0.f;p[j][1]=0.f;p[j][2]=0.f;p[j][3]=0.f; }
    for(int half=0; half<2; half++){
        __syncthreads();
        for(int i=threadIdx.x;i<4096;i+=256){ int o=i>>6,k=i&63; wshT[k][o]=w1[(half*64+o)*64+k]; }
        __syncthreads();
        float acc[4][4];
        #pragma unroll
        for(int a=0;a<4;a++){ acc[a][0]=0.f;acc[a][1]=0.f;acc[a][2]=0.f;acc[a][3]=0.f; }
        for(int k=0;k<64;k++){
            float4 v4 = *(const float4*)&vsh[k][si];
            float4 wv = *(const float4*)&wshT[k][o0];
            acc[0][0]+=wv.x*v4.x; acc[0][1]+=wv.x*v4.y; acc[0][2]+=wv.x*v4.z; acc[0][3]+=wv.x*v4.w;
            acc[1][0]+=wv.y*v4.x; acc[1][1]+=wv.y*v4.y; acc[1][2]+=wv.y*v4.z; acc[1][3]+=wv.y*v4.w;
            acc[2][0]+=wv.z*v4.x; acc[2][1]+=wv.z*v4.y; acc[2][2]+=wv.z*v4.z; acc[2][3]+=wv.z*v4.w;
            acc[3][0]+=wv.w*v4.x; acc[3][1]+=wv.w*v4.y; acc[3][2]+=wv.w*v4.z; acc[3][3]+=wv.w*v4.w;
        }
        #pragma unroll
        for(int oi=0;oi<4;oi++){
            int o = half*64 + o0 + oi;
            float bb = __ldg(&b1[o]);
            #pragma unroll
            for(int sx=0;sx<4;sx++){
                float u = gelu_f(acc[oi][sx] + bb);
                p[0][sx] += u*w2s[0][o];
                p[1][sx] += u*w2s[1][o];
                p[2][sx] += u*w2s[2][o];
            }
        }
    }
    #pragma unroll
    for(int j=0;j<3;j++){
        red[og][j][si+0]=p[j][0]; red[og][j][si+1]=p[j][1];
        red[og][j][si+2]=p[j][2]; red[og][j][si+3]=p[j][3];
    }
    __syncthreads();
    if(threadIdx.x < 64){
        int ss = threadIdx.x;
        #pragma unroll
        for(int j=0;j<3;j++){
            float acc = __ldg(&b2[j]);
            #pragma unroll
            for(int gq=0;gq<16;gq++) acc += red[gq][j][ss];
            out[(size_t)j*S3 + s0 + ss] = acc;
        }
    }
}

// ---------------- launch ----------------
extern "C" void kernel_launch(void* const* d_in, const int* in_sizes, int n_in,
                              void* d_out, int out_size){
    const float* x      = (const float*)d_in[0];
    const float* latent = (const float*)d_in[1];
    const float* lift_w = (const float*)d_in[2];
    const float* lift_b = (const float*)d_in[3];
    const float* sc_w1  = (const float*)d_in[4];
    const float* sc_w2  = (const float*)d_in[5];
    const float* sc_w3  = (const float*)d_in[6];
    const float* sc_w4  = (const float*)d_in[7];
    const float* conv_w = (const float*)d_in[8];
    const float* conv_b = (const float*)d_in[9];
    const float* gn_g   = (const float*)d_in[10];
    const float* gn_b   = (const float*)d_in[11];
    const float* p1_w   = (const float*)d_in[12];
    const float* p1_b   = (const float*)d_in[13];
    const float* p2_w   = (const float*)d_in[14];
    const float* p2_b   = (const float*)d_in[15];
    const float* c1_w   = (const float*)d_in[16];
    const float* c1_b   = (const float*)d_in[17];
    const float* c2_w   = (const float*)d_in[18];
    const float* c2_b   = (const float*)d_in[19];
    float* out = (float*)d_out;

    // Order chosen so the ncu capture (launch index 5 == 4th launch here) lands on fwdWH_k.
    init_tables_k<<<6,256>>>();
    film1_k<<<128,256>>>(latent, c1_w, c1_b);
    lift_conv_k<<<2048,256>>>(x, lift_w, lift_b, conv_w, conv_b);

    const size_t WOFF = (size_t)64*64*12*12*12*2;
    for(int l=0;l<3;l++){
        fwdWH_k<<<dim3(64,64),128>>>();
        if(l==0) film2_k<<<48,256>>>(c2_w, c2_b);
        fwdD_k<<<dim3(24,64),128>>>();
        mix_k<<<dim3(108,8),256>>>(sc_w1 + l*WOFF, sc_w2 + l*WOFF,
                                   sc_w3 + l*WOFF, sc_w4 + l*WOFF);
        invD_k<<<dim3(24,64),128>>>();
        invHW_gn_k<<<dim3(64,64),128>>>();
        gn_final_k<<<1,32>>>();
        if(l<2)
            gn_apply_conv_k<<<2048,256>>>(gn_g + l*64, gn_b + l*64, l,
                                          conv_w + (l+1)*4096, conv_b + (l+1)*64);
        else
            gn_apply_head_k<<<4096,256>>>(gn_g + l*64, gn_b + l*64, l,
                                          p1_w, p1_b, p2_w, p2_b, out);
    }
}